// round 6
// baseline (speedup 1.0000x reference)
#include <cuda_runtime.h>
#include <math.h>
#include <stdint.h>

#define VV 50257
#define DD 128
#define NN 256
#define LL 2
#define BB 8
#define SS 256
#define MM (BB*SS)          // 2048
#define RESN 4096
#define HOFF ((size_t)MM * VV)

#define PHI_F 1.6180339887498949f
#define CSC_F 651.8986469044033f          // RES / (2*pi)
#define ANG_F 0.0015339807878856412f      // 2*pi / RES

// ---------------- scratch (static device memory; no allocations) -----------
__device__ float2 g_tab[RESN];
__device__ float  g_X[MM * DD];
__device__ float  g_Wt [LL * DD * NN];   // [l][k][j]  (transposed layer_W)
__device__ float  g_Wrt[LL * NN * DD];   // [l][j][d]  (transposed layer_Wr)
__device__ float  g_Wit[LL * NN * DD];   // [l][j][d]  (transposed layer_Wi)

// ------- ARM optimized-routines AdvSIMD sinf/cosf (glibc libmvec) ----------
// Hypothesis: reference (JAX on aarch64 CPU) vectorized jnp.sin/jnp.cos via
// glibc's _ZGVnN4v_sinf/_cosf = AOR AdvSIMD implementations (1.886 ulp).
// Reconstructed with identical FMA chains; NEON FMLA/FMLS == CUDA fmaf bits.
#define AOR_INVPI  0x1.45f306p-2f
#define AOR_PI1    0x1.921fb6p+1f
#define AOR_PI2   -0x1.777a5cp-24f
#define AOR_PI3   -0x1.ee59dap-49f
#define AOR_SHIFT  0x1.8p+23f
#define AOR_P0    -0x1.555548p-3f
#define AOR_P1     0x1.110df4p-7f
#define AOR_P2    -0x1.9f42eap-13f
#define AOR_P3     0x1.5b2e76p-19f

__device__ __forceinline__ float aor_sin_core(float r, unsigned odd) {
    // r = reduced arg; y = r + (poly(r2)*r2)*r; sign-flip via XOR with odd<<31
    float r2 = __fmul_rn(r, r);
    float y  = __fmaf_rn(AOR_P3, r2, AOR_P2);
    y = __fmaf_rn(y, r2, AOR_P1);
    y = __fmaf_rn(y, r2, AOR_P0);
    y = __fmaf_rn(__fmul_rn(y, r2), r, r);
    return __uint_as_float(__float_as_uint(y) ^ odd);
}

__device__ __forceinline__ float aor_sinf(float x) {
    // n = rint(x/pi) via magic-shift (single fma rounding, ties-even)
    float nf = __fmaf_rn(x, AOR_INVPI, AOR_SHIFT);
    unsigned odd = __float_as_uint(nf) << 31;
    float n = __fsub_rn(nf, AOR_SHIFT);
    float r = __fmaf_rn(-AOR_PI1, n, x);
    r = __fmaf_rn(-AOR_PI2, n, r);
    r = __fmaf_rn(-AOR_PI3, n, r);
    return aor_sin_core(r, odd);
}

__device__ __forceinline__ float aor_cosf(float x) {
    float r0 = fabsf(x);
    // n = rint(|x|/pi + 0.5) - 0.5 ; parity of the rounded integer gives sign
    float nf = __fmaf_rn(r0, AOR_INVPI, 0.5f);
    float t  = __fadd_rn(nf, AOR_SHIFT);        // roundeven to integer
    unsigned odd = __float_as_uint(t) << 31;
    float n = __fsub_rn(__fsub_rn(t, AOR_SHIFT), 0.5f);
    float r = __fmaf_rn(-AOR_PI1, n, r0);
    r = __fmaf_rn(-AOR_PI2, n, r);
    r = __fmaf_rn(-AOR_PI3, n, r);
    return aor_sin_core(r, odd);
}

// ---------------- K0: sin/cos table + weight transposes --------------------
__global__ void k_init(const float* __restrict__ W,
                       const float* __restrict__ Wr,
                       const float* __restrict__ Wi) {
    int i = blockIdx.x * blockDim.x + threadIdx.x;
    if (i < RESN) {
        float ang = __fmul_rn((float)i, ANG_F);   // f32 angle, same as reference
        g_tab[i] = make_float2(aor_sinf(ang), aor_cosf(ang));
    }
    int o = i - RESN;
    if (o >= 0 && o < LL*NN*DD) {
        int l = o >> 15, k = (o >> 8) & (DD-1), j = o & (NN-1);
        g_Wt[o] = W[l*32768 + j*DD + k];
    }
    int o2 = o - LL*NN*DD;
    if (o2 >= 0 && o2 < LL*NN*DD) {
        int l = o2 >> 15, j = (o2 >> 7) & (NN-1), d = o2 & (DD-1);
        g_Wrt[o2] = Wr[l*32768 + d*NN + j];
    }
    int o3 = o2 - LL*NN*DD;
    if (o3 >= 0 && o3 < LL*NN*DD) {
        int l = o3 >> 15, j = (o3 >> 7) & (NN-1), d = o3 & (DD-1);
        g_Wit[o3] = Wi[l*32768 + d*NN + j];
    }
}

// ---------------- K1: elementwise recurrence -> X0, final h ----------------
// Theta path written with explicit round-to-nearest intrinsics: bitwise equal
// to the R3/R4-validated behavior (h_real 1.2e-5) and immune to contraction.
__global__ void k_recur(const int* __restrict__ ids,
                        const float* __restrict__ emb,
                        float* __restrict__ out) {
    __shared__ float2 stab[RESN];
    __shared__ int    sids[SS];
    const int b = blockIdx.x;     // 8 blocks
    const int d = threadIdx.x;    // 128 threads
    for (int i = threadIdx.x; i < RESN; i += 128) stab[i] = g_tab[i];
    for (int i = threadIdx.x; i < SS; i += 128)   sids[i] = ids[b*SS + i];
    __syncthreads();

    float hr = 0.f, hi = 0.f;
    int id0 = sids[0];
    float w  = emb[(size_t)id0*(2*DD) + d];
    float be = emb[(size_t)id0*(2*DD) + DD + d];

    for (int t = 0; t < SS; t++) {
        float wn = 0.f, bn = 0.f;
        if (t + 1 < SS) {
            int idn = sids[t+1];
            wn = emb[(size_t)idn*(2*DD) + d];
            bn = emb[(size_t)idn*(2*DD) + DD + d];
        }
        // theta = ((h_r+h_i)/(1+|w|) + b) + t*phi   (exact reference op order)
        float div   = __fdiv_rn(__fadd_rn(hr, hi), __fadd_rn(1.0f, fabsf(w)));
        float tphi  = __fmul_rn((float)t, PHI_F);
        float theta = __fadd_rn(__fadd_rn(div, be), tphi);
        int ii = __float2int_rn(__fmul_rn(theta, CSC_F)) & (RESN - 1);
        float2 sc = stab[ii];
        hi = sc.x; hr = sc.y;
        g_X[(b*SS + t)*DD + d] = __fadd_rn(hr, hi);
        w = wn; be = bn;
    }
    out[HOFF + b*DD + d]           = hr;
    out[HOFF + BB*DD + b*DD + d]   = hi;
}

// ---------------- K2: fused 2-layer MLP over 2048 independent rows ---------
#define TM 8
__global__ __launch_bounds__(256) void k_mlp(const float* __restrict__ bvec) {
    __shared__ __align__(16) float xs[TM][DD];
    __shared__ __align__(16) float cs[TM][NN];
    __shared__ __align__(16) float sn[TM][NN];
    const int tid = threadIdx.x;
    const int r0  = blockIdx.x * TM;

    for (int i = tid; i < TM*DD; i += 256)
        xs[i >> 7][i & (DD-1)] = g_X[(r0 + (i >> 7))*DD + (i & (DD-1))];

    for (int l = 0; l < LL; l++) {
        __syncthreads();
        // ---- phase 1: th[r][j] for j = tid, all TM rows
        float acc[TM];
        #pragma unroll
        for (int r = 0; r < TM; r++) acc[r] = 0.f;
        const float* wt = g_Wt + l*DD*NN;
        #pragma unroll 2
        for (int k4 = 0; k4 < DD/4; k4++) {
            float4 xv[TM];
            #pragma unroll
            for (int r = 0; r < TM; r++)
                xv[r] = ((const float4*)xs[r])[k4];
            #pragma unroll
            for (int kk = 0; kk < 4; kk++) {
                float wv = wt[(k4*4 + kk)*NN + tid];
                #pragma unroll
                for (int r = 0; r < TM; r++) {
                    float x = (kk == 0) ? xv[r].x : (kk == 1) ? xv[r].y :
                              (kk == 2) ? xv[r].z : xv[r].w;
                    acc[r] += x * wv;
                }
            }
        }
        float bj = bvec[l*NN + tid];
        #pragma unroll
        for (int r = 0; r < TM; r++) {
            float tphi = (float)((r0 + r) & (SS-1)) * PHI_F;
            float th = (acc[r] + bj) + tphi;
            int ii = __float2int_rn(th * CSC_F) & (RESN - 1);
            float2 sc = g_tab[ii];
            sn[r][tid] = sc.x;
            cs[r][tid] = sc.y;
        }
        __syncthreads();
        // ---- phase 2: o[r][d] = cs@Wr.T + sn@Wi.T, then x += silu(o)
        const int dg = tid & 31;    // 4 consecutive d per thread
        const int r  = tid >> 5;    // one row per warp
        const float4* wr4 = (const float4*)(g_Wrt + l*NN*DD);
        const float4* wi4 = (const float4*)(g_Wit + l*NN*DD);
        float o0 = 0.f, o1 = 0.f, o2 = 0.f, o3 = 0.f;
        #pragma unroll 2
        for (int j4 = 0; j4 < NN/4; j4++) {
            float4 cv = ((const float4*)cs[r])[j4];
            float4 sv = ((const float4*)sn[r])[j4];
            #pragma unroll
            for (int jj = 0; jj < 4; jj++) {
                int j = j4*4 + jj;
                float4 a  = wr4[j*(DD/4) + dg];
                float4 b2 = wi4[j*(DD/4) + dg];
                float c = (jj == 0) ? cv.x : (jj == 1) ? cv.y : (jj == 2) ? cv.z : cv.w;
                float s = (jj == 0) ? sv.x : (jj == 1) ? sv.y : (jj == 2) ? sv.z : sv.w;
                o0 += c*a.x + s*b2.x;
                o1 += c*a.y + s*b2.y;
                o2 += c*a.z + s*b2.z;
                o3 += c*a.w + s*b2.w;
            }
        }
        int dbase = dg * 4;
        float ov[4] = {o0, o1, o2, o3};
        #pragma unroll
        for (int q = 0; q < 4; q++) {
            float o = ov[q];
            float sg = 1.0f / (1.0f + expf(-o));
            xs[r][dbase + q] += o * sg;
        }
    }
    __syncthreads();
    for (int i = tid; i < TM*DD; i += 256)
        g_X[(r0 + (i >> 7))*DD + (i & (DD-1))] = xs[i >> 7][i & (DD-1)];
}

// ---------------- K3: logits GEMM (M=2048, N=50257, K=128), tf32 mma.sync --
#define PA 132
#define K3_SMEM (2*128*PA*4)    // 135168 bytes dynamic smem

__device__ __forceinline__ unsigned f2tf32(float v) {
    unsigned u;
    asm("cvt.rna.tf32.f32 %0, %1;" : "=r"(u) : "f"(v));
    return u;
}

__global__ __launch_bounds__(256) void k_gemm(const float* __restrict__ Bmat,
                                              float* __restrict__ out) {
    extern __shared__ unsigned smemu[];
    unsigned* As = smemu;              // 128 x PA (tf32 bits) = 67584 B
    unsigned* Bs = smemu + 128*PA;     // 128 x PA
    float*    Os = (float*)smemu;      // aliases As region, pitch 129 (66048B <= 67584B)

    const int tid  = threadIdx.x;
    const int n0   = blockIdx.x * 128;
    const int warp = tid >> 5, lane = tid & 31;
    const int grp  = lane >> 2, tig = lane & 3;
    const int wm   = (warp >> 2) * 64;   // warp row base (0 or 64)
    const int wn   = (warp & 3) * 32;    // warp col base (0,32,64,96)

    // load B tile once: Bs[n][k] = tf32(out_w[n0+n][k]); X tiles are L2-resident
    for (int i = tid; i < 128*128; i += 256) {
        int n = i >> 7, k = i & 127;
        float v = (n0 + n < VV) ? Bmat[(size_t)(n0 + n)*DD + k] : 0.f;
        Bs[n*PA + k] = f2tf32(v);
    }

    for (int mt = 0; mt < MM/128; mt++) {
        const int m0 = mt * 128;
        __syncthreads();   // prev-iter Os copy done (Os aliases As); B ready
        for (int i = tid; i < 128*128; i += 256) {
            int r = i >> 7, k = i & 127;
            As[r*PA + k] = f2tf32(g_X[(m0 + r)*DD + k]);
        }
        __syncthreads();

        float acc[4][4][4];
        #pragma unroll
        for (int mi = 0; mi < 4; mi++)
            #pragma unroll
            for (int ni = 0; ni < 4; ni++)
                #pragma unroll
                for (int q = 0; q < 4; q++) acc[mi][ni][q] = 0.f;

        #pragma unroll
        for (int kk = 0; kk < 16; kk++) {
            const int k0 = kk * 8;
            unsigned a[4][4];
            #pragma unroll
            for (int mi = 0; mi < 4; mi++) {
                const unsigned* ap = As + (wm + mi*16 + grp)*PA + k0 + tig;
                a[mi][0] = ap[0];
                a[mi][1] = ap[8*PA];
                a[mi][2] = ap[4];
                a[mi][3] = ap[8*PA + 4];
            }
            #pragma unroll
            for (int ni = 0; ni < 4; ni++) {
                const unsigned* bp = Bs + (wn + ni*8 + grp)*PA + k0 + tig;
                unsigned b0 = bp[0], b1 = bp[4];
                #pragma unroll
                for (int mi = 0; mi < 4; mi++) {
                    asm volatile(
                        "mma.sync.aligned.m16n8k8.row.col.f32.tf32.tf32.f32 "
                        "{%0,%1,%2,%3}, {%4,%5,%6,%7}, {%8,%9}, {%0,%1,%2,%3};"
                        : "+f"(acc[mi][ni][0]), "+f"(acc[mi][ni][1]),
                          "+f"(acc[mi][ni][2]), "+f"(acc[mi][ni][3])
                        : "r"(a[mi][0]), "r"(a[mi][1]), "r"(a[mi][2]), "r"(a[mi][3]),
                          "r"(b0), "r"(b1));
                }
            }
        }
        __syncthreads();   // all As reads done before Os (alias) is written
        #pragma unroll
        for (int mi = 0; mi < 4; mi++) {
            #pragma unroll
            for (int ni = 0; ni < 4; ni++) {
                int rr = wm + mi*16 + grp;
                int cc = wn + ni*8 + 2*tig;
                Os[rr*129 + cc]       = acc[mi][ni][0];
                Os[rr*129 + cc + 1]   = acc[mi][ni][1];
                Os[(rr+8)*129 + cc]   = acc[mi][ni][2];
                Os[(rr+8)*129 + cc+1] = acc[mi][ni][3];
            }
        }
        __syncthreads();
        for (int i = tid; i < 128*128; i += 256) {
            int r = i >> 7, c = i & 127;
            int col = n0 + c;
            if (col < VV)
                out[(size_t)(m0 + r)*VV + col] = Os[r*129 + c];
        }
    }
}

// ---------------- launch ---------------------------------------------------
extern "C" void kernel_launch(void* const* d_in, const int* in_sizes, int n_in,
                              void* d_out, int out_size) {
    const int*   ids = (const int*)  d_in[0];
    const float* emb = (const float*)d_in[1];
    const float* W   = (const float*)d_in[2];
    const float* bv  = (const float*)d_in[3];
    const float* Wr  = (const float*)d_in[4];
    const float* Wi  = (const float*)d_in[5];
    const float* ow  = (const float*)d_in[6];
    float* out = (float*)d_out;

    (void)cudaFuncSetAttribute(k_gemm, cudaFuncAttributeMaxDynamicSharedMemorySize, K3_SMEM);

    k_init <<<784, 256>>>(W, Wr, Wi);      // 784*256 = 200704 = 4096 + 3*65536
    k_recur<<<BB, 128>>>(ids, emb, out);
    k_mlp  <<<MM/TM, 256>>>(bv);
    k_gemm <<<(VV + 127)/128, 256, K3_SMEM>>>(ow, out);
}

// round 7
// speedup vs baseline: 1.4995x; 1.4995x over previous
#include <cuda_runtime.h>
#include <math.h>
#include <stdint.h>

#define VV 50257
#define DD 128
#define NN 256
#define LL 2
#define BB 8
#define SS 256
#define MM (BB*SS)          // 2048
#define RESN 4096
#define HOFF ((size_t)MM * VV)

#define PHI_F 1.6180339887498949f
#define CSC_F 651.8986469044033f          // RES / (2*pi)
#define ANG_F 0.0015339807878856412f      // 2*pi / RES

// ---------------- scratch (static device memory; no allocations) -----------
__device__ float2 g_tab[RESN];
__device__ float  g_X[MM * DD];
__device__ float  g_Wt [LL * DD * NN];   // [l][k][j]  (transposed layer_W)
__device__ float  g_Wrt[LL * NN * DD];   // [l][j][d]  (transposed layer_Wr)
__device__ float  g_Wit[LL * NN * DD];   // [l][j][d]  (transposed layer_Wi)

// ------- ARM optimized-routines AdvSIMD sinf/cosf (glibc libmvec) ----------
// VALIDATED in R6 (passed). Do not modify.
#define AOR_INVPI  0x1.45f306p-2f
#define AOR_PI1    0x1.921fb6p+1f
#define AOR_PI2   -0x1.777a5cp-24f
#define AOR_PI3   -0x1.ee59dap-49f
#define AOR_SHIFT  0x1.8p+23f
#define AOR_P0    -0x1.555548p-3f
#define AOR_P1     0x1.110df4p-7f
#define AOR_P2    -0x1.9f42eap-13f
#define AOR_P3     0x1.5b2e76p-19f

__device__ __forceinline__ float aor_sin_core(float r, unsigned odd) {
    float r2 = __fmul_rn(r, r);
    float y  = __fmaf_rn(AOR_P3, r2, AOR_P2);
    y = __fmaf_rn(y, r2, AOR_P1);
    y = __fmaf_rn(y, r2, AOR_P0);
    y = __fmaf_rn(__fmul_rn(y, r2), r, r);
    return __uint_as_float(__float_as_uint(y) ^ odd);
}

__device__ __forceinline__ float aor_sinf(float x) {
    float nf = __fmaf_rn(x, AOR_INVPI, AOR_SHIFT);
    unsigned odd = __float_as_uint(nf) << 31;
    float n = __fsub_rn(nf, AOR_SHIFT);
    float r = __fmaf_rn(-AOR_PI1, n, x);
    r = __fmaf_rn(-AOR_PI2, n, r);
    r = __fmaf_rn(-AOR_PI3, n, r);
    return aor_sin_core(r, odd);
}

__device__ __forceinline__ float aor_cosf(float x) {
    float r0 = fabsf(x);
    float nf = __fmaf_rn(r0, AOR_INVPI, 0.5f);
    float t  = __fadd_rn(nf, AOR_SHIFT);
    unsigned odd = __float_as_uint(t) << 31;
    float n = __fsub_rn(__fsub_rn(t, AOR_SHIFT), 0.5f);
    float r = __fmaf_rn(-AOR_PI1, n, r0);
    r = __fmaf_rn(-AOR_PI2, n, r);
    r = __fmaf_rn(-AOR_PI3, n, r);
    return aor_sin_core(r, odd);
}

// ---------------- K0: sin/cos table + weight transposes --------------------
__global__ void k_init(const float* __restrict__ W,
                       const float* __restrict__ Wr,
                       const float* __restrict__ Wi) {
    int i = blockIdx.x * blockDim.x + threadIdx.x;
    if (i < RESN) {
        float ang = __fmul_rn((float)i, ANG_F);
        g_tab[i] = make_float2(aor_sinf(ang), aor_cosf(ang));
    }
    int o = i - RESN;
    if (o >= 0 && o < LL*NN*DD) {
        int l = o >> 15, k = (o >> 8) & (DD-1), j = o & (NN-1);
        g_Wt[o] = W[l*32768 + j*DD + k];
    }
    int o2 = o - LL*NN*DD;
    if (o2 >= 0 && o2 < LL*NN*DD) {
        int l = o2 >> 15, j = (o2 >> 7) & (NN-1), d = o2 & (DD-1);
        g_Wrt[o2] = Wr[l*32768 + d*NN + j];
    }
    int o3 = o2 - LL*NN*DD;
    if (o3 >= 0 && o3 < LL*NN*DD) {
        int l = o3 >> 15, j = (o3 >> 7) & (NN-1), d = o3 & (DD-1);
        g_Wit[o3] = Wi[l*32768 + d*NN + j];
    }
}

// ---------------- K1: elementwise recurrence -> X0, final h ----------------
// VALIDATED in R6 (passed). Do not modify.
__global__ void k_recur(const int* __restrict__ ids,
                        const float* __restrict__ emb,
                        float* __restrict__ out) {
    __shared__ float2 stab[RESN];
    __shared__ int    sids[SS];
    const int b = blockIdx.x;     // 8 blocks
    const int d = threadIdx.x;    // 128 threads
    for (int i = threadIdx.x; i < RESN; i += 128) stab[i] = g_tab[i];
    for (int i = threadIdx.x; i < SS; i += 128)   sids[i] = ids[b*SS + i];
    __syncthreads();

    float hr = 0.f, hi = 0.f;
    int id0 = sids[0];
    float w  = emb[(size_t)id0*(2*DD) + d];
    float be = emb[(size_t)id0*(2*DD) + DD + d];

    for (int t = 0; t < SS; t++) {
        float wn = 0.f, bn = 0.f;
        if (t + 1 < SS) {
            int idn = sids[t+1];
            wn = emb[(size_t)idn*(2*DD) + d];
            bn = emb[(size_t)idn*(2*DD) + DD + d];
        }
        float div   = __fdiv_rn(__fadd_rn(hr, hi), __fadd_rn(1.0f, fabsf(w)));
        float tphi  = __fmul_rn((float)t, PHI_F);
        float theta = __fadd_rn(__fadd_rn(div, be), tphi);
        int ii = __float2int_rn(__fmul_rn(theta, CSC_F)) & (RESN - 1);
        float2 sc = stab[ii];
        hi = sc.x; hr = sc.y;
        g_X[(b*SS + t)*DD + d] = __fadd_rn(hr, hi);
        w = wn; be = bn;
    }
    out[HOFF + b*DD + d]           = hr;
    out[HOFF + BB*DD + b*DD + d]   = hi;
}

// ---------------- K2: fused 2-layer MLP over 2048 independent rows ---------
#define TM 8
__global__ __launch_bounds__(256) void k_mlp(const float* __restrict__ bvec) {
    __shared__ __align__(16) float xs[TM][DD];
    __shared__ __align__(16) float cs[TM][NN];
    __shared__ __align__(16) float sn[TM][NN];
    const int tid = threadIdx.x;
    const int r0  = blockIdx.x * TM;

    for (int i = tid; i < TM*DD; i += 256)
        xs[i >> 7][i & (DD-1)] = g_X[(r0 + (i >> 7))*DD + (i & (DD-1))];

    for (int l = 0; l < LL; l++) {
        __syncthreads();
        float acc[TM];
        #pragma unroll
        for (int r = 0; r < TM; r++) acc[r] = 0.f;
        const float* wt = g_Wt + l*DD*NN;
        #pragma unroll 2
        for (int k4 = 0; k4 < DD/4; k4++) {
            float4 xv[TM];
            #pragma unroll
            for (int r = 0; r < TM; r++)
                xv[r] = ((const float4*)xs[r])[k4];
            #pragma unroll
            for (int kk = 0; kk < 4; kk++) {
                float wv = wt[(k4*4 + kk)*NN + tid];
                #pragma unroll
                for (int r = 0; r < TM; r++) {
                    float x = (kk == 0) ? xv[r].x : (kk == 1) ? xv[r].y :
                              (kk == 2) ? xv[r].z : xv[r].w;
                    acc[r] += x * wv;
                }
            }
        }
        float bj = bvec[l*NN + tid];
        #pragma unroll
        for (int r = 0; r < TM; r++) {
            float tphi = (float)((r0 + r) & (SS-1)) * PHI_F;
            float th = (acc[r] + bj) + tphi;
            int ii = __float2int_rn(th * CSC_F) & (RESN - 1);
            float2 sc = g_tab[ii];
            sn[r][tid] = sc.x;
            cs[r][tid] = sc.y;
        }
        __syncthreads();
        const int dg = tid & 31;
        const int r  = tid >> 5;
        const float4* wr4 = (const float4*)(g_Wrt + l*NN*DD);
        const float4* wi4 = (const float4*)(g_Wit + l*NN*DD);
        float o0 = 0.f, o1 = 0.f, o2 = 0.f, o3 = 0.f;
        #pragma unroll 2
        for (int j4 = 0; j4 < NN/4; j4++) {
            float4 cv = ((const float4*)cs[r])[j4];
            float4 sv = ((const float4*)sn[r])[j4];
            #pragma unroll
            for (int jj = 0; jj < 4; jj++) {
                int j = j4*4 + jj;
                float4 a  = wr4[j*(DD/4) + dg];
                float4 b2 = wi4[j*(DD/4) + dg];
                float c = (jj == 0) ? cv.x : (jj == 1) ? cv.y : (jj == 2) ? cv.z : cv.w;
                float s = (jj == 0) ? sv.x : (jj == 1) ? sv.y : (jj == 2) ? sv.z : sv.w;
                o0 += c*a.x + s*b2.x;
                o1 += c*a.y + s*b2.y;
                o2 += c*a.z + s*b2.z;
                o3 += c*a.w + s*b2.w;
            }
        }
        int dbase = dg * 4;
        float ov[4] = {o0, o1, o2, o3};
        #pragma unroll
        for (int q = 0; q < 4; q++) {
            float o = ov[q];
            float sg = 1.0f / (1.0f + expf(-o));
            xs[r][dbase + q] += o * sg;
        }
    }
    __syncthreads();
    for (int i = tid; i < TM*DD; i += 256)
        g_X[(r0 + (i >> 7))*DD + (i & (DD-1))] = xs[i >> 7][i & (DD-1)];
}

// ---------------- K3: logits GEMM (M=2048, N=50257, K=128), tf32 mma.sync --
// v2: 2 CTAs/SM (As chunk 64 rows -> 101KB smem), 32x32 warp tiles,
// direct predicated STG.32 epilogue (V odd => no vector stores possible),
// M split in half across CTA pairs to reduce wave quantization.
#define PA 132
#define K3_SMEM ((64*PA + 128*PA)*4)     // 101376 B -> 2 CTAs/SM

__device__ __forceinline__ unsigned f2tf32(float v) {
    unsigned u;
    asm("cvt.rna.tf32.f32 %0, %1;" : "=r"(u) : "f"(v));
    return u;
}

__global__ __launch_bounds__(256, 2) void k_gemm(const float* __restrict__ Bmat,
                                                 float* __restrict__ out) {
    extern __shared__ unsigned smemu[];
    unsigned* As = smemu;              // 64 x PA (tf32 bits)
    unsigned* Bs = smemu + 64*PA;      // 128 x PA

    const int tid  = threadIdx.x;
    const int nt   = blockIdx.x >> 1;      // n-tile 0..392
    const int mh   = blockIdx.x & 1;       // M half
    const int n0   = nt * 128;
    const int warp = tid >> 5, lane = tid & 31;
    const int grp  = lane >> 2, tig = lane & 3;
    const int wm   = (warp >> 2) * 32;     // warp row base (0 or 32)
    const int wn   = (warp & 3) * 32;      // warp col base (0,32,64,96)

    // load B tile once: Bs[n][k] = tf32(out_w[n0+n][k])  (float4 LDG)
    for (int i = tid; i < 128*32; i += 256) {
        int n = i >> 5, k4 = i & 31;
        unsigned* bp = Bs + n*PA + k4*4;
        if (n0 + n < VV) {
            float4 v = ((const float4*)(Bmat + (size_t)(n0 + n)*DD))[k4];
            bp[0] = f2tf32(v.x); bp[1] = f2tf32(v.y);
            bp[2] = f2tf32(v.z); bp[3] = f2tf32(v.w);
        } else {
            bp[0] = 0u; bp[1] = 0u; bp[2] = 0u; bp[3] = 0u;
        }
    }

    for (int ms = 0; ms < 16; ms++) {
        const int m0 = (mh*16 + ms) * 64;
        __syncthreads();   // As reads of prev iter done; (iter0: B ready)
        for (int i = tid; i < 64*32; i += 256) {
            int r = i >> 5, k4 = i & 31;
            float4 v = ((const float4*)(g_X + (m0 + r)*DD))[k4];
            unsigned* ap = As + r*PA + k4*4;
            ap[0] = f2tf32(v.x); ap[1] = f2tf32(v.y);
            ap[2] = f2tf32(v.z); ap[3] = f2tf32(v.w);
        }
        __syncthreads();

        float acc[2][4][4];
        #pragma unroll
        for (int mi = 0; mi < 2; mi++)
            #pragma unroll
            for (int ni = 0; ni < 4; ni++)
                #pragma unroll
                for (int q = 0; q < 4; q++) acc[mi][ni][q] = 0.f;

        #pragma unroll
        for (int kk = 0; kk < 16; kk++) {
            const int k0 = kk * 8;
            unsigned a[2][4];
            #pragma unroll
            for (int mi = 0; mi < 2; mi++) {
                const unsigned* ap = As + (wm + mi*16 + grp)*PA + k0 + tig;
                a[mi][0] = ap[0];
                a[mi][1] = ap[8*PA];
                a[mi][2] = ap[4];
                a[mi][3] = ap[8*PA + 4];
            }
            #pragma unroll
            for (int ni = 0; ni < 4; ni++) {
                const unsigned* bp = Bs + (wn + ni*8 + grp)*PA + k0 + tig;
                unsigned b0 = bp[0], b1 = bp[4];
                #pragma unroll
                for (int mi = 0; mi < 2; mi++) {
                    asm volatile(
                        "mma.sync.aligned.m16n8k8.row.col.f32.tf32.tf32.f32 "
                        "{%0,%1,%2,%3}, {%4,%5,%6,%7}, {%8,%9}, {%0,%1,%2,%3};"
                        : "+f"(acc[mi][ni][0]), "+f"(acc[mi][ni][1]),
                          "+f"(acc[mi][ni][2]), "+f"(acc[mi][ni][3])
                        : "r"(a[mi][0]), "r"(a[mi][1]), "r"(a[mi][2]), "r"(a[mi][3]),
                          "r"(b0), "r"(b1));
                }
            }
        }

        // direct epilogue: scalar stores (VV odd => rows arbitrarily aligned)
        #pragma unroll
        for (int mi = 0; mi < 2; mi++) {
            #pragma unroll
            for (int ni = 0; ni < 4; ni++) {
                int rr  = wm + mi*16 + grp;
                int col = n0 + wn + ni*8 + 2*tig;
                float* p0 = out + (size_t)(m0 + rr)*VV + col;
                float* p1 = out + (size_t)(m0 + rr + 8)*VV + col;
                if (col + 1 < VV) {
                    p0[0] = acc[mi][ni][0]; p0[1] = acc[mi][ni][1];
                    p1[0] = acc[mi][ni][2]; p1[1] = acc[mi][ni][3];
                } else if (col < VV) {
                    p0[0] = acc[mi][ni][0];
                    p1[0] = acc[mi][ni][2];
                }
            }
        }
    }
}

// ---------------- launch ---------------------------------------------------
extern "C" void kernel_launch(void* const* d_in, const int* in_sizes, int n_in,
                              void* d_out, int out_size) {
    const int*   ids = (const int*)  d_in[0];
    const float* emb = (const float*)d_in[1];
    const float* W   = (const float*)d_in[2];
    const float* bv  = (const float*)d_in[3];
    const float* Wr  = (const float*)d_in[4];
    const float* Wi  = (const float*)d_in[5];
    const float* ow  = (const float*)d_in[6];
    float* out = (float*)d_out;

    (void)cudaFuncSetAttribute(k_gemm, cudaFuncAttributeMaxDynamicSharedMemorySize, K3_SMEM);

    k_init <<<784, 256>>>(W, Wr, Wi);      // 784*256 = 200704 = 4096 + 3*65536
    k_recur<<<BB, 128>>>(ids, emb, out);
    k_mlp  <<<MM/TM, 256>>>(bv);
    k_gemm <<<2*((VV + 127)/128), 256, K3_SMEM>>>(ow, out);
}

// round 8
// speedup vs baseline: 1.5010x; 1.0010x over previous
#include <cuda_runtime.h>
#include <math.h>
#include <stdint.h>

#define VV 50257
#define DD 128
#define NN 256
#define LL 2
#define BB 8
#define SS 256
#define MM (BB*SS)          // 2048
#define RESN 4096
#define HOFF ((size_t)MM * VV)

#define PHI_F 1.6180339887498949f
#define CSC_F 651.8986469044033f          // RES / (2*pi)
#define ANG_F 0.0015339807878856412f      // 2*pi / RES

// ---------------- scratch (static device memory; no allocations) -----------
__device__ float2 g_tab[RESN];
__device__ float  g_X[MM * DD];
__device__ float  g_Wt [LL * DD * NN];   // [l][k][j]  (transposed layer_W)
__device__ float  g_Wrt[LL * NN * DD];   // [l][j][d]  (transposed layer_Wr)
__device__ float  g_Wit[LL * NN * DD];   // [l][j][d]  (transposed layer_Wi)

// ------- ARM optimized-routines AdvSIMD sinf/cosf (glibc libmvec) ----------
// VALIDATED in R6 (passed). Do not modify.
#define AOR_INVPI  0x1.45f306p-2f
#define AOR_PI1    0x1.921fb6p+1f
#define AOR_PI2   -0x1.777a5cp-24f
#define AOR_PI3   -0x1.ee59dap-49f
#define AOR_SHIFT  0x1.8p+23f
#define AOR_P0    -0x1.555548p-3f
#define AOR_P1     0x1.110df4p-7f
#define AOR_P2    -0x1.9f42eap-13f
#define AOR_P3     0x1.5b2e76p-19f

__device__ __forceinline__ float aor_sin_core(float r, unsigned odd) {
    float r2 = __fmul_rn(r, r);
    float y  = __fmaf_rn(AOR_P3, r2, AOR_P2);
    y = __fmaf_rn(y, r2, AOR_P1);
    y = __fmaf_rn(y, r2, AOR_P0);
    y = __fmaf_rn(__fmul_rn(y, r2), r, r);
    return __uint_as_float(__float_as_uint(y) ^ odd);
}

__device__ __forceinline__ float aor_sinf(float x) {
    float nf = __fmaf_rn(x, AOR_INVPI, AOR_SHIFT);
    unsigned odd = __float_as_uint(nf) << 31;
    float n = __fsub_rn(nf, AOR_SHIFT);
    float r = __fmaf_rn(-AOR_PI1, n, x);
    r = __fmaf_rn(-AOR_PI2, n, r);
    r = __fmaf_rn(-AOR_PI3, n, r);
    return aor_sin_core(r, odd);
}

__device__ __forceinline__ float aor_cosf(float x) {
    float r0 = fabsf(x);
    float nf = __fmaf_rn(r0, AOR_INVPI, 0.5f);
    float t  = __fadd_rn(nf, AOR_SHIFT);
    unsigned odd = __float_as_uint(t) << 31;
    float n = __fsub_rn(__fsub_rn(t, AOR_SHIFT), 0.5f);
    float r = __fmaf_rn(-AOR_PI1, n, r0);
    r = __fmaf_rn(-AOR_PI2, n, r);
    r = __fmaf_rn(-AOR_PI3, n, r);
    return aor_sin_core(r, odd);
}

// ---------------- K0: sin/cos table + weight transposes --------------------
__global__ void k_init(const float* __restrict__ W,
                       const float* __restrict__ Wr,
                       const float* __restrict__ Wi) {
    int i = blockIdx.x * blockDim.x + threadIdx.x;
    if (i < RESN) {
        float ang = __fmul_rn((float)i, ANG_F);
        g_tab[i] = make_float2(aor_sinf(ang), aor_cosf(ang));
    }
    int o = i - RESN;
    if (o >= 0 && o < LL*NN*DD) {
        int l = o >> 15, k = (o >> 8) & (DD-1), j = o & (NN-1);
        g_Wt[o] = W[l*32768 + j*DD + k];
    }
    int o2 = o - LL*NN*DD;
    if (o2 >= 0 && o2 < LL*NN*DD) {
        int l = o2 >> 15, j = (o2 >> 7) & (NN-1), d = o2 & (DD-1);
        g_Wrt[o2] = Wr[l*32768 + d*NN + j];
    }
    int o3 = o2 - LL*NN*DD;
    if (o3 >= 0 && o3 < LL*NN*DD) {
        int l = o3 >> 15, j = (o3 >> 7) & (NN-1), d = o3 & (DD-1);
        g_Wit[o3] = Wi[l*32768 + d*NN + j];
    }
}

// ---------------- K1: elementwise recurrence -> X0, final h ----------------
// VALIDATED in R6 (passed). Do not modify.
__global__ void k_recur(const int* __restrict__ ids,
                        const float* __restrict__ emb,
                        float* __restrict__ out) {
    __shared__ float2 stab[RESN];
    __shared__ int    sids[SS];
    const int b = blockIdx.x;     // 8 blocks
    const int d = threadIdx.x;    // 128 threads
    for (int i = threadIdx.x; i < RESN; i += 128) stab[i] = g_tab[i];
    for (int i = threadIdx.x; i < SS; i += 128)   sids[i] = ids[b*SS + i];
    __syncthreads();

    float hr = 0.f, hi = 0.f;
    int id0 = sids[0];
    float w  = emb[(size_t)id0*(2*DD) + d];
    float be = emb[(size_t)id0*(2*DD) + DD + d];

    for (int t = 0; t < SS; t++) {
        float wn = 0.f, bn = 0.f;
        if (t + 1 < SS) {
            int idn = sids[t+1];
            wn = emb[(size_t)idn*(2*DD) + d];
            bn = emb[(size_t)idn*(2*DD) + DD + d];
        }
        float div   = __fdiv_rn(__fadd_rn(hr, hi), __fadd_rn(1.0f, fabsf(w)));
        float tphi  = __fmul_rn((float)t, PHI_F);
        float theta = __fadd_rn(__fadd_rn(div, be), tphi);
        int ii = __float2int_rn(__fmul_rn(theta, CSC_F)) & (RESN - 1);
        float2 sc = stab[ii];
        hi = sc.x; hr = sc.y;
        g_X[(b*SS + t)*DD + d] = __fadd_rn(hr, hi);
        w = wn; be = bn;
    }
    out[HOFF + b*DD + d]           = hr;
    out[HOFF + BB*DD + b*DD + d]   = hi;
}

// ---------------- K2: fused 2-layer MLP over 2048 independent rows ---------
#define TM 8
__global__ __launch_bounds__(256) void k_mlp(const float* __restrict__ bvec) {
    __shared__ __align__(16) float xs[TM][DD];
    __shared__ __align__(16) float cs[TM][NN];
    __shared__ __align__(16) float sn[TM][NN];
    const int tid = threadIdx.x;
    const int r0  = blockIdx.x * TM;

    for (int i = tid; i < TM*DD; i += 256)
        xs[i >> 7][i & (DD-1)] = g_X[(r0 + (i >> 7))*DD + (i & (DD-1))];

    for (int l = 0; l < LL; l++) {
        __syncthreads();
        float acc[TM];
        #pragma unroll
        for (int r = 0; r < TM; r++) acc[r] = 0.f;
        const float* wt = g_Wt + l*DD*NN;
        #pragma unroll 2
        for (int k4 = 0; k4 < DD/4; k4++) {
            float4 xv[TM];
            #pragma unroll
            for (int r = 0; r < TM; r++)
                xv[r] = ((const float4*)xs[r])[k4];
            #pragma unroll
            for (int kk = 0; kk < 4; kk++) {
                float wv = wt[(k4*4 + kk)*NN + tid];
                #pragma unroll
                for (int r = 0; r < TM; r++) {
                    float x = (kk == 0) ? xv[r].x : (kk == 1) ? xv[r].y :
                              (kk == 2) ? xv[r].z : xv[r].w;
                    acc[r] += x * wv;
                }
            }
        }
        float bj = bvec[l*NN + tid];
        #pragma unroll
        for (int r = 0; r < TM; r++) {
            float tphi = (float)((r0 + r) & (SS-1)) * PHI_F;
            float th = (acc[r] + bj) + tphi;
            int ii = __float2int_rn(th * CSC_F) & (RESN - 1);
            float2 sc = g_tab[ii];
            sn[r][tid] = sc.x;
            cs[r][tid] = sc.y;
        }
        __syncthreads();
        const int dg = tid & 31;
        const int r  = tid >> 5;
        const float4* wr4 = (const float4*)(g_Wrt + l*NN*DD);
        const float4* wi4 = (const float4*)(g_Wit + l*NN*DD);
        float o0 = 0.f, o1 = 0.f, o2 = 0.f, o3 = 0.f;
        #pragma unroll 2
        for (int j4 = 0; j4 < NN/4; j4++) {
            float4 cv = ((const float4*)cs[r])[j4];
            float4 sv = ((const float4*)sn[r])[j4];
            #pragma unroll
            for (int jj = 0; jj < 4; jj++) {
                int j = j4*4 + jj;
                float4 a  = wr4[j*(DD/4) + dg];
                float4 b2 = wi4[j*(DD/4) + dg];
                float c = (jj == 0) ? cv.x : (jj == 1) ? cv.y : (jj == 2) ? cv.z : cv.w;
                float s = (jj == 0) ? sv.x : (jj == 1) ? sv.y : (jj == 2) ? sv.z : sv.w;
                o0 += c*a.x + s*b2.x;
                o1 += c*a.y + s*b2.y;
                o2 += c*a.z + s*b2.z;
                o3 += c*a.w + s*b2.w;
            }
        }
        int dbase = dg * 4;
        float ov[4] = {o0, o1, o2, o3};
        #pragma unroll
        for (int q = 0; q < 4; q++) {
            float o = ov[q];
            float sg = 1.0f / (1.0f + expf(-o));
            xs[r][dbase + q] += o * sg;
        }
    }
    __syncthreads();
    for (int i = tid; i < TM*DD; i += 256)
        g_X[(r0 + (i >> 7))*DD + (i & (DD-1))] = xs[i >> 7][i & (DD-1)];
}

// ---------------- K3: logits GEMM (M=2048, N=50257, K=128), tf32 mma.sync --
// v3: ldmatrix fragment loads (tf32 via b16 pairs) + persistent fine-grained
// scheduling (grid=296=2*148, items = 393 n-tiles x 32 m-chunks, contiguous
// nt-major ranges per CTA -> B reload only at nt boundaries, ~99% wave eff).
#define PA 132
#define K3_SMEM ((64*PA + 128*PA)*4)     // 101376 B -> 2 CTAs/SM
#define K3_GRID 296
#define K3_ITEMS (393*32)                // 12576

__device__ __forceinline__ unsigned f2tf32(float v) {
    unsigned u;
    asm("cvt.rna.tf32.f32 %0, %1;" : "=r"(u) : "f"(v));
    return u;
}
__device__ __forceinline__ void ldsm_x4(unsigned& r0, unsigned& r1,
                                        unsigned& r2, unsigned& r3, unsigned addr) {
    asm volatile("ldmatrix.sync.aligned.m8n8.x4.shared.b16 {%0,%1,%2,%3}, [%4];"
                 : "=r"(r0), "=r"(r1), "=r"(r2), "=r"(r3) : "r"(addr));
}
__device__ __forceinline__ void ldsm_x2(unsigned& r0, unsigned& r1, unsigned addr) {
    asm volatile("ldmatrix.sync.aligned.m8n8.x2.shared.b16 {%0,%1}, [%2];"
                 : "=r"(r0), "=r"(r1) : "r"(addr));
}

__global__ __launch_bounds__(256, 2) void k_gemm(const float* __restrict__ Bmat,
                                                 float* __restrict__ out) {
    extern __shared__ unsigned smemu[];
    unsigned* As = smemu;              // 64 x PA (tf32 bits)
    unsigned* Bs = smemu + 64*PA;      // 128 x PA

    const int tid  = threadIdx.x;
    const int warp = tid >> 5, lane = tid & 31;
    const int grp  = lane >> 2, tig = lane & 3;
    const int wm   = (warp >> 2) * 32;     // warp row base (0 or 32)
    const int wn   = (warp & 3) * 32;      // warp col base (0,32,64,96)

    const unsigned sbase  = (unsigned)__cvta_generic_to_shared(smemu);
    const unsigned as_u32 = sbase;
    const unsigned bs_u32 = sbase + 64*PA*4;

    // per-lane ldmatrix base addresses (row/col-group mapping; see R8 notes)
    const unsigned aBase0 = as_u32 + (unsigned)((wm + (lane & 15))*PA)*4u
                                   + (unsigned)(lane >> 4)*16u;       // mi=0
    const unsigned aBase1 = aBase0 + 16u*PA*4u;                       // mi=1
    const unsigned bBase  = bs_u32 + (unsigned)((wn + (lane & 7))*PA)*4u
                                   + (unsigned)((lane >> 3) & 1)*16u; // ni=0

    // persistent contiguous work partition
    const int start = (int)(((long long)blockIdx.x       * K3_ITEMS) / K3_GRID);
    const int stop  = (int)(((long long)(blockIdx.x + 1) * K3_ITEMS) / K3_GRID);
    int cur_nt = -1;

    for (int item = start; item < stop; item++) {
        const int nt = item >> 5;          // n-tile (items nt-major)
        const int mc = item & 31;          // m-chunk of 64 rows
        const int n0 = nt * 128;
        const int m0 = mc * 64;

        if (nt != cur_nt) {
            __syncthreads();               // prior MMA reads of Bs done
            for (int i = tid; i < 128*32; i += 256) {
                int n = i >> 5, k4 = i & 31;
                unsigned* bp = Bs + n*PA + k4*4;
                if (n0 + n < VV) {
                    float4 v = ((const float4*)(Bmat + (size_t)(n0 + n)*DD))[k4];
                    bp[0] = f2tf32(v.x); bp[1] = f2tf32(v.y);
                    bp[2] = f2tf32(v.z); bp[3] = f2tf32(v.w);
                } else {
                    bp[0] = 0u; bp[1] = 0u; bp[2] = 0u; bp[3] = 0u;
                }
            }
            cur_nt = nt;
        }

        __syncthreads();                   // prior As reads done; Bs visible
        for (int i = tid; i < 64*32; i += 256) {
            int r = i >> 5, k4 = i & 31;
            float4 v = ((const float4*)(g_X + (m0 + r)*DD))[k4];
            unsigned* ap = As + r*PA + k4*4;
            ap[0] = f2tf32(v.x); ap[1] = f2tf32(v.y);
            ap[2] = f2tf32(v.z); ap[3] = f2tf32(v.w);
        }
        __syncthreads();

        float acc[2][4][4];
        #pragma unroll
        for (int mi = 0; mi < 2; mi++)
            #pragma unroll
            for (int ni = 0; ni < 4; ni++)
                #pragma unroll
                for (int q = 0; q < 4; q++) acc[mi][ni][q] = 0.f;

        #pragma unroll
        for (int kk = 0; kk < 16; kk++) {
            const unsigned koff = kk * 32u;   // 8 tf32 = 32 bytes per k-step
            unsigned a[2][4];
            ldsm_x4(a[0][0], a[0][1], a[0][2], a[0][3], aBase0 + koff);
            ldsm_x4(a[1][0], a[1][1], a[1][2], a[1][3], aBase1 + koff);
            #pragma unroll
            for (int ni = 0; ni < 4; ni++) {
                unsigned b0, b1;
                ldsm_x2(b0, b1, bBase + (unsigned)ni*(8u*PA*4u) + koff);
                #pragma unroll
                for (int mi = 0; mi < 2; mi++) {
                    asm volatile(
                        "mma.sync.aligned.m16n8k8.row.col.f32.tf32.tf32.f32 "
                        "{%0,%1,%2,%3}, {%4,%5,%6,%7}, {%8,%9}, {%0,%1,%2,%3};"
                        : "+f"(acc[mi][ni][0]), "+f"(acc[mi][ni][1]),
                          "+f"(acc[mi][ni][2]), "+f"(acc[mi][ni][3])
                        : "r"(a[mi][0]), "r"(a[mi][1]), "r"(a[mi][2]), "r"(a[mi][3]),
                          "r"(b0), "r"(b1));
                }
            }
        }

        // direct epilogue: scalar stores (VV odd => rows arbitrarily aligned)
        #pragma unroll
        for (int mi = 0; mi < 2; mi++) {
            #pragma unroll
            for (int ni = 0; ni < 4; ni++) {
                int rr  = wm + mi*16 + grp;
                int col = n0 + wn + ni*8 + 2*tig;
                float* p0 = out + (size_t)(m0 + rr)*VV + col;
                float* p1 = out + (size_t)(m0 + rr + 8)*VV + col;
                if (col + 1 < VV) {
                    p0[0] = acc[mi][ni][0]; p0[1] = acc[mi][ni][1];
                    p1[0] = acc[mi][ni][2]; p1[1] = acc[mi][ni][3];
                } else if (col < VV) {
                    p0[0] = acc[mi][ni][0];
                    p1[0] = acc[mi][ni][2];
                }
            }
        }
    }
}

// ---------------- launch ---------------------------------------------------
extern "C" void kernel_launch(void* const* d_in, const int* in_sizes, int n_in,
                              void* d_out, int out_size) {
    const int*   ids = (const int*)  d_in[0];
    const float* emb = (const float*)d_in[1];
    const float* W   = (const float*)d_in[2];
    const float* bv  = (const float*)d_in[3];
    const float* Wr  = (const float*)d_in[4];
    const float* Wi  = (const float*)d_in[5];
    const float* ow  = (const float*)d_in[6];
    float* out = (float*)d_out;

    (void)cudaFuncSetAttribute(k_gemm, cudaFuncAttributeMaxDynamicSharedMemorySize, K3_SMEM);

    k_init <<<784, 256>>>(W, Wr, Wi);      // 784*256 = 200704 = 4096 + 3*65536
    k_recur<<<BB, 128>>>(ids, emb, out);
    k_mlp  <<<MM/TM, 256>>>(bv);
    k_gemm <<<K3_GRID, 256, K3_SMEM>>>(ow, out);
}